// round 1
// baseline (speedup 1.0000x reference)
#include <cuda_runtime.h>
#include <cstdint>

// Zero-fill the [B, N] float32 output with 16B stores, grid-stride.
__global__ void zero_fill_kernel(float4* __restrict__ out4, long long n4) {
    long long i = (long long)blockIdx.x * blockDim.x + threadIdx.x;
    long long stride = (long long)gridDim.x * blockDim.x;
    float4 z = make_float4(0.f, 0.f, 0.f, 0.f);
    for (; i < n4; i += stride) {
        out4[i] = z;
    }
}

// Scatter-add: out[b, idx[j]] += in[b, j].
// idx_raw may be int32 or int64; detect by checking the odd 32-bit words
// (int64 of small non-negative values => all odd words zero; the strided
// int32 index pattern cannot have 4 consecutive odd indices all zero).
__global__ void scatter_add_kernel(const float* __restrict__ in,
                                   const void* __restrict__ idx_raw,
                                   float* __restrict__ out,
                                   int B, int K, long long N) {
    long long t = (long long)blockIdx.x * blockDim.x + threadIdx.x;
    long long total = (long long)B * K;
    if (t >= total) return;

    int b = (int)(t / K);
    int j = (int)(t % K);

    const unsigned int* w = (const unsigned int*)idx_raw;
    // Detection: works uniformly across all threads (same data), no divergence.
    // Guard small K: only look at words that exist for the int32 interpretation.
    bool is64;
    if (K >= 8) {
        is64 = ((w[1] | w[3] | w[5] | w[7]) == 0u);
    } else if (K >= 2) {
        is64 = (w[1] == 0u);
    } else {
        is64 = false;  // K==1: treat as int32; idx value read below either way
    }

    long long col;
    if (is64) {
        col = ((const long long*)idx_raw)[j];
    } else {
        col = (long long)((const int*)idx_raw)[j];
    }

    float v = in[(long long)b * K + j];
    atomicAdd(&out[(long long)b * N + col], v);
}

extern "C" void kernel_launch(void* const* d_in, const int* in_sizes, int n_in,
                              void* d_out, int out_size) {
    const float* inputs = (const float*)d_in[0];
    const void* idx = d_in[1];
    float* out = (float*)d_out;

    int total_in = in_sizes[0];   // B * K
    int K = in_sizes[1];          // number of observed indices
    int B = total_in / K;
    long long N = (long long)out_size / B;  // nodes per batch row (output is [B, N, 1])

    // 1) Zero fill (out_size = 102,400,000 is divisible by 4).
    long long n4 = (long long)out_size / 4;
    int threads = 256;
    long long blocks_ll = (n4 + threads - 1) / threads;
    int blocks = (blocks_ll > 0x7FFFFFF0LL) ? 0x7FFFFFF0 : (int)blocks_ll;
    zero_fill_kernel<<<blocks, threads>>>((float4*)out, n4);
    // Handle any non-multiple-of-4 tail via the same kernel contract: out_size
    // here is 2048*50000 which is divisible by 4, but be safe:
    long long tail_start = n4 * 4;
    if (tail_start < (long long)out_size) {
        // tiny tail: reuse scatter grid shape with a lambda-free approach —
        // simplest is a 1-block memset-style kernel inline:
        // (cheap: at most 3 elements)
        cudaMemsetAsync(out + tail_start, 0,
                        ((long long)out_size - tail_start) * sizeof(float), 0);
    }

    // 2) Scatter-add the observed columns.
    long long total = (long long)B * K;
    int sblocks = (int)((total + threads - 1) / threads);
    scatter_add_kernel<<<sblocks, threads>>>(inputs, idx, out, B, K, N);
}

// round 4
// speedup vs baseline: 1.3906x; 1.3906x over previous
#include <cuda_runtime.h>
#include <cstdint>

// Inverse map scratch: inv[n] = j such that idx[j] == n, else -1.
#define INV_CAP (1 << 20)
__device__ int g_inv[INV_CAP];

__device__ __forceinline__ bool detect_is64(const unsigned int* w, int K) {
    // int64 small non-negative indices => all odd 32-bit words are zero.
    if (K >= 8) return ((w[1] | w[3] | w[5] | w[7]) == 0u);
    if (K >= 2) return (w[1] == 0u);
    return false;
}

__device__ __forceinline__ int load_idx(const void* idx_raw, int j, bool is64) {
    return is64 ? (int)((const long long*)idx_raw)[j]
                : ((const int*)idx_raw)[j];
}

__global__ void init_inv_kernel(int n) {
    int i = blockIdx.x * blockDim.x + threadIdx.x;
    if (i < n) g_inv[i] = -1;
}

__global__ void build_inv_kernel(const void* __restrict__ idx_raw, int K) {
    int j = blockIdx.x * blockDim.x + threadIdx.x;
    if (j >= K) return;
    bool is64 = detect_is64((const unsigned int*)idx_raw, K);
    int col = load_idx(idx_raw, j, is64);
    atomicExch(&g_inv[col], j);  // any winner; losers fixed up later
}

// Single streaming pass: out[b, n] = (inv[n] >= 0) ? in[b, inv[n]] : 0.
// Each thread owns one 4-column group across ROWS batch rows.
__global__ void fused_write_kernel(const float* __restrict__ in,
                                   float* __restrict__ out,
                                   int B, int N, int K, int rows_per_thread,
                                   int vec_ok) {
    int n_groups = (N + 3) >> 2;
    int g = blockIdx.x * blockDim.x + threadIdx.x;
    if (g >= n_groups) return;
    int n0 = g * 4;

    int b0 = blockIdx.y * rows_per_thread;
    int bend = b0 + rows_per_thread;
    if (bend > B) bend = B;

    if (vec_ok && n0 + 4 <= N) {
        int4 iv = *reinterpret_cast<const int4*>(&g_inv[n0]);
        bool anyhit = (iv.x >= 0) | (iv.y >= 0) | (iv.z >= 0) | (iv.w >= 0);
        float4 z = make_float4(0.f, 0.f, 0.f, 0.f);
        if (!anyhit) {
            #pragma unroll 4
            for (int b = b0; b < bend; b++) {
                float4* p = reinterpret_cast<float4*>(out + (long long)b * N + n0);
                __stcs(p, z);
            }
        } else {
            for (int b = b0; b < bend; b++) {
                const float* rb = in + (long long)b * K;
                float4 v;
                v.x = (iv.x >= 0) ? __ldg(rb + iv.x) : 0.f;
                v.y = (iv.y >= 0) ? __ldg(rb + iv.y) : 0.f;
                v.z = (iv.z >= 0) ? __ldg(rb + iv.z) : 0.f;
                v.w = (iv.w >= 0) ? __ldg(rb + iv.w) : 0.f;
                float4* p = reinterpret_cast<float4*>(out + (long long)b * N + n0);
                __stcs(p, v);
            }
        }
    } else {
        // Scalar tail / unaligned fallback.
        for (int c = n0; c < n0 + 4 && c < N; c++) {
            int j = g_inv[c];
            for (int b = b0; b < bend; b++) {
                float v = (j >= 0) ? in[(long long)b * K + j] : 0.f;
                out[(long long)b * N + c] = v;
            }
        }
    }
}

// Duplicate-index fixup: any j that lost the atomicExch race adds its
// contribution for every batch row. No-op when indices are unique.
__global__ void fixup_dup_kernel(const float* __restrict__ in,
                                 const void* __restrict__ idx_raw,
                                 float* __restrict__ out,
                                 int B, int K, int N) {
    int j = blockIdx.x * blockDim.x + threadIdx.x;
    if (j >= K) return;
    bool is64 = detect_is64((const unsigned int*)idx_raw, K);
    int col = load_idx(idx_raw, j, is64);
    if (g_inv[col] != j) {
        for (int b = 0; b < B; b++) {
            atomicAdd(&out[(long long)b * N + col], in[(long long)b * K + j]);
        }
    }
}

// ---- Fallback path (N too large for inv map): fill + atomic scatter ----
__global__ void zero_fill_kernel(float4* __restrict__ out4, long long n4) {
    long long i = (long long)blockIdx.x * blockDim.x + threadIdx.x;
    long long stride = (long long)gridDim.x * blockDim.x;
    float4 z = make_float4(0.f, 0.f, 0.f, 0.f);
    for (; i < n4; i += stride) out4[i] = z;
}

__global__ void scatter_add_kernel(const float* __restrict__ in,
                                   const void* __restrict__ idx_raw,
                                   float* __restrict__ out,
                                   int B, int K, long long N) {
    long long t = (long long)blockIdx.x * blockDim.x + threadIdx.x;
    long long total = (long long)B * K;
    if (t >= total) return;
    int b = (int)(t / K);
    int j = (int)(t % K);
    bool is64 = detect_is64((const unsigned int*)idx_raw, K);
    long long col = load_idx(idx_raw, j, is64);
    atomicAdd(&out[(long long)b * N + col], in[(long long)b * K + j]);
}

extern "C" void kernel_launch(void* const* d_in, const int* in_sizes, int n_in,
                              void* d_out, int out_size) {
    const float* inputs = (const float*)d_in[0];
    const void* idx = d_in[1];
    float* out = (float*)d_out;

    int total_in = in_sizes[0];   // B * K
    int K = in_sizes[1];          // observed count
    int B = total_in / K;
    long long Nll = (long long)out_size / B;
    int N = (int)Nll;

    if (Nll <= INV_CAP) {
        // 1) inv[n] = -1
        init_inv_kernel<<<(N + 255) / 256, 256>>>(N);
        // 2) inv[idx[j]] = j
        build_inv_kernel<<<(K + 255) / 256, 256>>>(idx, K);
        // 3) single fused streaming write of the whole output
        const int ROWS = 8;
        int n_groups = (N + 3) / 4;
        int vec_ok = ((N & 3) == 0) ? 1 : 0;
        dim3 block(256, 1, 1);
        dim3 grid((n_groups + 255) / 256, (B + ROWS - 1) / ROWS, 1);
        fused_write_kernel<<<grid, block>>>(inputs, out, B, N, K, ROWS, vec_ok);
        // 4) duplicate-index correction (no-op for unique indices)
        fixup_dup_kernel<<<(K + 255) / 256, 256>>>(inputs, idx, out, B, K, N);
    } else {
        // Fallback: zero-fill + atomic scatter.
        long long n4 = (long long)out_size / 4;
        int threads = 256;
        long long blocks_ll = (n4 + threads - 1) / threads;
        int blocks = (blocks_ll > 0x7FFFFFF0LL) ? 0x7FFFFFF0 : (int)blocks_ll;
        zero_fill_kernel<<<blocks, threads>>>((float4*)out, n4);
        long long tail_start = n4 * 4;
        if (tail_start < (long long)out_size) {
            cudaMemsetAsync(out + tail_start, 0,
                            ((long long)out_size - tail_start) * sizeof(float), 0);
        }
        long long total = (long long)B * K;
        int sblocks = (int)((total + threads - 1) / threads);
        scatter_add_kernel<<<sblocks, threads>>>(inputs, idx, out, B, K, Nll);
    }
}